// round 2
// baseline (speedup 1.0000x reference)
#include <cuda_runtime.h>
#include <math.h>

// Problem constants
#define Bn 16384
#define Dn 1024
#define Hn 2048
#define En 4
#define Cn 3
#define EPSv 1e-5f

// GEMM tiling
#define BM 128
#define BN 128
#define BK 16
#define TM 8
#define TN 8

// -------- scratch (static device memory; no allocation allowed) --------
__device__ float g_normed[(size_t)Bn * Dn];          // 64 MB
__device__ float g_w1p[(size_t)En * Dn * Hn];        // 32 MB  (ln_g-folded W1)
__device__ float g_b1p[En * Hn];                     // folded bias
__device__ float g_gw[Bn * En];                      // softmax gate weights
__device__ float g_acc[(size_t)En * Bn * Cn];        // partial logits (pre-b2)

// ---------------------------------------------------------------------
// Kernel 0: zero the logit accumulator (graph-replay safe)
// ---------------------------------------------------------------------
__global__ void zero_acc_kernel() {
    int i = blockIdx.x * 256 + threadIdx.x;
    if (i < En * Bn * Cn) g_acc[i] = 0.0f;
}

// ---------------------------------------------------------------------
// Kernel 1: fold per-expert LN affine into W1 / b1
//   w1p[e,d,h] = ln_g[e,d] * w1[e,d,h]
//   b1p[e,h]   = b1[e,h] + sum_d ln_b[e,d] * w1[e,d,h]
// grid: (Hn/256, En), 256 threads
// ---------------------------------------------------------------------
__global__ void prep_w1_kernel(const float* __restrict__ ex_ln_g,
                               const float* __restrict__ ex_ln_b,
                               const float* __restrict__ ex_w1,
                               const float* __restrict__ ex_b1) {
    __shared__ float sg[Dn];
    __shared__ float sb[Dn];
    int e = blockIdx.y;
    int h = blockIdx.x * 256 + threadIdx.x;
    for (int i = threadIdx.x; i < Dn; i += 256) {
        sg[i] = ex_ln_g[e * Dn + i];
        sb[i] = ex_ln_b[e * Dn + i];
    }
    __syncthreads();

    const float* w  = ex_w1 + (size_t)e * Dn * Hn + h;
    float*       wo = g_w1p + (size_t)e * Dn * Hn + h;
    float sum = 0.0f;
#pragma unroll 4
    for (int d = 0; d < Dn; d++) {
        float v = w[(size_t)d * Hn];
        wo[(size_t)d * Hn] = sg[d] * v;
        sum = fmaf(sb[d], v, sum);
    }
    g_b1p[e * Hn + h] = ex_b1[e * Hn + h] + sum;
}

// ---------------------------------------------------------------------
// Kernel 2: per-row normalize + gate logits + softmax
// grid: Bn blocks, 256 threads (each thread handles 4 contiguous elems)
// ---------------------------------------------------------------------
__global__ void norm_gate_kernel(const float* __restrict__ x,
                                 const float* __restrict__ gln_g,
                                 const float* __restrict__ gln_b,
                                 const float* __restrict__ gate_w,
                                 const float* __restrict__ gate_b) {
    int row = blockIdx.x;
    int t = threadIdx.x;
    int lid = t & 31, wid = t >> 5;

    float4 v = ((const float4*)(x + (size_t)row * Dn))[t];
    float xv[4] = {v.x, v.y, v.z, v.w};
    float s = xv[0] + xv[1] + xv[2] + xv[3];
    float ss = xv[0]*xv[0] + xv[1]*xv[1] + xv[2]*xv[2] + xv[3]*xv[3];

#pragma unroll
    for (int o = 16; o > 0; o >>= 1) {
        s  += __shfl_down_sync(0xffffffffu, s,  o);
        ss += __shfl_down_sync(0xffffffffu, ss, o);
    }
    __shared__ float red0[8], red1[8];
    if (lid == 0) { red0[wid] = s; red1[wid] = ss; }
    __syncthreads();
    __shared__ float s_mean, s_rstd;
    if (t == 0) {
        float a = 0.0f, b2 = 0.0f;
#pragma unroll
        for (int i = 0; i < 8; i++) { a += red0[i]; b2 += red1[i]; }
        float m = a * (1.0f / Dn);
        float var = b2 * (1.0f / Dn) - m * m;
        s_mean = m;
        s_rstd = rsqrtf(var + EPSv);
    }
    __syncthreads();
    float m = s_mean, r = s_rstd;

    float nn[4];
#pragma unroll
    for (int i = 0; i < 4; i++) nn[i] = (xv[i] - m) * r;
    float4 nv = make_float4(nn[0], nn[1], nn[2], nn[3]);
    ((float4*)(g_normed + (size_t)row * Dn))[t] = nv;

    // gate: (normed*g + b) @ gate_w   (gate_w is [Dn, En], En=4 -> float4 per row)
    float gl[4] = {0, 0, 0, 0};
    int d0 = t * 4;
#pragma unroll
    for (int i = 0; i < 4; i++) {
        int d = d0 + i;
        float tt = fmaf(nn[i], gln_g[d], gln_b[d]);
        float4 w4 = ((const float4*)gate_w)[d];
        gl[0] = fmaf(tt, w4.x, gl[0]);
        gl[1] = fmaf(tt, w4.y, gl[1]);
        gl[2] = fmaf(tt, w4.z, gl[2]);
        gl[3] = fmaf(tt, w4.w, gl[3]);
    }
#pragma unroll
    for (int e = 0; e < 4; e++)
#pragma unroll
        for (int o = 16; o > 0; o >>= 1)
            gl[e] += __shfl_down_sync(0xffffffffu, gl[e], o);

    __shared__ float gred[8][4];
    if (lid == 0)
#pragma unroll
        for (int e = 0; e < 4; e++) gred[wid][e] = gl[e];
    __syncthreads();
    if (t == 0) {
        float lg[4];
#pragma unroll
        for (int e = 0; e < 4; e++) {
            float a = gate_b[e];
#pragma unroll
            for (int w = 0; w < 8; w++) a += gred[w][e];
            lg[e] = a;
        }
        float mx = fmaxf(fmaxf(lg[0], lg[1]), fmaxf(lg[2], lg[3]));
        float ex[4], den = 0.0f;
#pragma unroll
        for (int e = 0; e < 4; e++) { ex[e] = expf(lg[e] - mx); den += ex[e]; }
        float inv = 1.0f / den;
#pragma unroll
        for (int e = 0; e < 4; e++) g_gw[row * 4 + e] = ex[e] * inv;
    }
}

// ---------------------------------------------------------------------
// Kernel 3: per-expert GEMM  (normed[B,D] @ w1p[D,H]) fused with
//   +b1p, exact GELU, and partial second GEMM (H -> C=3) into g_acc.
// grid: (Hn/BN, Bn/BM, En), 256 threads, 8x8 microtile per thread.
// ---------------------------------------------------------------------
__global__ void __launch_bounds__(256, 2)
moe_gemm_kernel(const float* __restrict__ ex_w2) {
    __shared__ float As[BK][BM + 4];   // transposed A tile; +4 keeps float4 alignment
    __shared__ float Bs[BK][BN];
    __shared__ float w2s[BN][Cn];
    __shared__ float b1s[BN];

    const int e  = blockIdx.z;
    const int n0 = blockIdx.x * BN;
    const int m0 = blockIdx.y * BM;
    const int t  = threadIdx.x;
    const int ty = t >> 4, tx = t & 15;

    for (int i = t; i < BN * Cn; i += 256)
        w2s[i / Cn][i % Cn] = ex_w2[((size_t)e * Hn + n0 + i / Cn) * Cn + (i % Cn)];
    for (int i = t; i < BN; i += 256)
        b1s[i] = g_b1p[e * Hn + n0 + i];

    const float* Ag = g_normed;
    const float* Bg = g_w1p + (size_t)e * Dn * Hn;

    // A tile: 128 rows x 16 k  -> each thread loads 2 float4 (rows ar0 and ar0+64)
    const int ar0 = t >> 2;
    const int ac4 = t & 3;          // which float4 within the 16-k row chunk
    // B tile: 16 k x 128 n     -> each thread loads 2 float4 (k rows bkr and bkr+8)
    const int bkr = t >> 5;
    const int bn4 = t & 31;

    float4 a0, a1, b0, b1;
    {
        const int k0 = 0;
        a0 = *(const float4*)(Ag + (size_t)(m0 + ar0)      * Dn + k0 + ac4 * 4);
        a1 = *(const float4*)(Ag + (size_t)(m0 + ar0 + 64) * Dn + k0 + ac4 * 4);
        b0 = *(const float4*)(Bg + (size_t)(k0 + bkr)     * Hn + n0 + bn4 * 4);
        b1 = *(const float4*)(Bg + (size_t)(k0 + bkr + 8) * Hn + n0 + bn4 * 4);
    }

    float acc[TM][TN];
#pragma unroll
    for (int i = 0; i < TM; i++)
#pragma unroll
        for (int j = 0; j < TN; j++) acc[i][j] = 0.0f;

    const int NK = Dn / BK;   // 64
    for (int kt = 0; kt < NK; kt++) {
        __syncthreads();
        // stage prefetched tiles into shared
        As[ac4 * 4 + 0][ar0] = a0.x;
        As[ac4 * 4 + 1][ar0] = a0.y;
        As[ac4 * 4 + 2][ar0] = a0.z;
        As[ac4 * 4 + 3][ar0] = a0.w;
        As[ac4 * 4 + 0][ar0 + 64] = a1.x;
        As[ac4 * 4 + 1][ar0 + 64] = a1.y;
        As[ac4 * 4 + 2][ar0 + 64] = a1.z;
        As[ac4 * 4 + 3][ar0 + 64] = a1.w;
        *(float4*)&Bs[bkr][bn4 * 4]     = b0;
        *(float4*)&Bs[bkr + 8][bn4 * 4] = b1;
        __syncthreads();

        if (kt + 1 < NK) {
            const int k0 = (kt + 1) * BK;
            a0 = *(const float4*)(Ag + (size_t)(m0 + ar0)      * Dn + k0 + ac4 * 4);
            a1 = *(const float4*)(Ag + (size_t)(m0 + ar0 + 64) * Dn + k0 + ac4 * 4);
            b0 = *(const float4*)(Bg + (size_t)(k0 + bkr)     * Hn + n0 + bn4 * 4);
            b1 = *(const float4*)(Bg + (size_t)(k0 + bkr + 8) * Hn + n0 + bn4 * 4);
        }

#pragma unroll
        for (int k = 0; k < BK; k++) {
            float af[TM], bf[TN];
            *(float4*)(af)     = *(const float4*)&As[k][ty * 8];
            *(float4*)(af + 4) = *(const float4*)&As[k][ty * 8 + 4];
            *(float4*)(bf)     = *(const float4*)&Bs[k][tx * 8];
            *(float4*)(bf + 4) = *(const float4*)&Bs[k][tx * 8 + 4];
#pragma unroll
            for (int i = 0; i < TM; i++)
#pragma unroll
                for (int j = 0; j < TN; j++)
                    acc[i][j] = fmaf(af[i], bf[j], acc[i][j]);
        }
    }

    // Epilogue: +bias, exact GELU, project to C=3, reduce across tx, atomicAdd
    float p[TM][Cn];
#pragma unroll
    for (int i = 0; i < TM; i++)
#pragma unroll
        for (int c = 0; c < Cn; c++) p[i][c] = 0.0f;

#pragma unroll
    for (int i = 0; i < TM; i++) {
#pragma unroll
        for (int j = 0; j < TN; j++) {
            const int n = tx * 8 + j;
            float hv = acc[i][j] + b1s[n];
            float ge = 0.5f * hv * (1.0f + erff(hv * 0.70710678118654752f));
            p[i][0] = fmaf(ge, w2s[n][0], p[i][0]);
            p[i][1] = fmaf(ge, w2s[n][1], p[i][1]);
            p[i][2] = fmaf(ge, w2s[n][2], p[i][2]);
        }
    }

#pragma unroll
    for (int i = 0; i < TM; i++) {
#pragma unroll
        for (int c = 0; c < Cn; c++) {
            float v = p[i][c];
            v += __shfl_down_sync(0xffffffffu, v, 8, 16);
            v += __shfl_down_sync(0xffffffffu, v, 4, 16);
            v += __shfl_down_sync(0xffffffffu, v, 2, 16);
            v += __shfl_down_sync(0xffffffffu, v, 1, 16);
            if (tx == 0) {
                const size_t row = (size_t)m0 + ty * 8 + i;
                atomicAdd(&g_acc[((size_t)e * Bn + row) * Cn + c], v);
            }
        }
    }
}

// ---------------------------------------------------------------------
// Kernel 4: out[b,c] = sum_e gw[b,e] * (acc[e,b,c] + b2[e,c])
// ---------------------------------------------------------------------
__global__ void finalize_kernel(const float* __restrict__ ex_b2,
                                float* __restrict__ out) {
    int idx = blockIdx.x * 256 + threadIdx.x;
    if (idx >= Bn * Cn) return;
    int b = idx / Cn, c = idx % Cn;
    float s = 0.0f;
#pragma unroll
    for (int e = 0; e < En; e++) {
        float logit = g_acc[((size_t)e * Bn + b) * Cn + c] + ex_b2[e * Cn + c];
        s = fmaf(g_gw[b * En + e], logit, s);
    }
    out[idx] = s;
}

// ---------------------------------------------------------------------
extern "C" void kernel_launch(void* const* d_in, const int* in_sizes, int n_in,
                              void* d_out, int out_size) {
    const float* x         = (const float*)d_in[0];
    const float* gate_ln_g = (const float*)d_in[1];
    const float* gate_ln_b = (const float*)d_in[2];
    const float* gate_w    = (const float*)d_in[3];
    const float* gate_b    = (const float*)d_in[4];
    const float* ex_ln_g   = (const float*)d_in[5];
    const float* ex_ln_b   = (const float*)d_in[6];
    const float* ex_w1     = (const float*)d_in[7];
    const float* ex_b1     = (const float*)d_in[8];
    const float* ex_w2     = (const float*)d_in[9];
    const float* ex_b2     = (const float*)d_in[10];
    float* out = (float*)d_out;

    zero_acc_kernel<<<(En * Bn * Cn + 255) / 256, 256>>>();
    prep_w1_kernel<<<dim3(Hn / 256, En), 256>>>(ex_ln_g, ex_ln_b, ex_w1, ex_b1);
    norm_gate_kernel<<<Bn, 256>>>(x, gate_ln_g, gate_ln_b, gate_w, gate_b);
    moe_gemm_kernel<<<dim3(Hn / BN, Bn / BM, En), 256>>>(ex_w2);
    finalize_kernel<<<(Bn * Cn + 255) / 256, 256>>>(ex_b2, out);
}

// round 10
// speedup vs baseline: 1.8437x; 1.8437x over previous
#include <cuda_runtime.h>
#include <cuda_bf16.h>
#include <math.h>
#include <cstdint>

// Problem constants
#define Bn 16384
#define Dn 1024
#define Hn 2048
#define En 4
#define Cn 3
#define EPSv 1e-5f

// GEMM tiling (mma.sync path — base-ISA tensor cores; tcgen05 unavailable on
// this build's compute_103 lowering)
#define BM 128
#define BN 128
#define BK 32
#define NSTG 4
#define ROWB 80                      // 32 bf16 = 64B payload + 16B pad (conflict-free ldmatrix)
#define TILE_B (128 * ROWB)          // 10240 B per operand tile
#define STAGE_B (4 * TILE_B)         // Ahi, Alo, Bhi, Blo = 40960 B
#define EXT_OFF (NSTG * STAGE_B)     // 163840
#define SMEM_TOTAL (EXT_OFF + 1536 + 512 + 1536)   // +sacc +b1s +w2s = 167424

// -------- scratch (static device memory; no allocation allowed) --------
__device__ __nv_bfloat16 g_ahi[(size_t)Bn * Dn];            // 32 MB
__device__ __nv_bfloat16 g_alo[(size_t)Bn * Dn];            // 32 MB
__device__ __nv_bfloat16 g_w1t_hi[(size_t)En * Hn * Dn];    // 16 MB  [e][h][d]
__device__ __nv_bfloat16 g_w1t_lo[(size_t)En * Hn * Dn];    // 16 MB
__device__ float g_b1p[En * Hn];                            // folded bias
__device__ float g_gw[Bn * En];                             // softmax gate weights
__device__ float g_acc[(size_t)En * Bn * Cn];               // partial logits (pre-b2)

// ======================= helpers =========================
__device__ __forceinline__ uint32_t smem_u32(const void* p) {
    uint32_t a;
    asm("{ .reg .u64 t; cvta.to.shared.u64 t, %1; cvt.u32.u64 %0, t; }" : "=r"(a) : "l"(p));
    return a;
}

__device__ __forceinline__ void cp16(uint32_t dst, const void* src) {
    asm volatile("cp.async.cg.shared.global [%0], [%1], 16;" :: "r"(dst), "l"(src));
}
#define CP_COMMIT() asm volatile("cp.async.commit_group;" ::: "memory")

__device__ __forceinline__ void ldsm4(uint32_t* r, uint32_t addr) {
    asm volatile("ldmatrix.sync.aligned.m8n8.x4.shared.b16 {%0,%1,%2,%3}, [%4];"
                 : "=r"(r[0]), "=r"(r[1]), "=r"(r[2]), "=r"(r[3]) : "r"(addr));
}

__device__ __forceinline__ void mma16816(float* d, const uint32_t* a, const uint32_t* b) {
    asm volatile(
        "mma.sync.aligned.m16n8k16.row.col.f32.bf16.bf16.f32 "
        "{%0,%1,%2,%3}, {%4,%5,%6,%7}, {%8,%9}, {%0,%1,%2,%3};"
        : "+f"(d[0]), "+f"(d[1]), "+f"(d[2]), "+f"(d[3])
        : "r"(a[0]), "r"(a[1]), "r"(a[2]), "r"(a[3]), "r"(b[0]), "r"(b[1]));
}

// ---------------------------------------------------------------------
// Kernel 0: zero g_acc, init b1p = ex_b1
// ---------------------------------------------------------------------
__global__ void init_kernel(const float* __restrict__ ex_b1) {
    int i = blockIdx.x * 256 + threadIdx.x;
    if (i < En * Bn * Cn) g_acc[i] = 0.0f;
    if (i < En * Hn) g_b1p[i] = ex_b1[i];
}

// ---------------------------------------------------------------------
// Kernel 1: fold LN affine into W1, transpose to [e][h][d], split bf16 hi/lo.
//   Also accumulate b1p[e,h] += sum_d ln_b[e,d] * w1[e,d,h]  (atomic partials)
// grid: (Dn/32, Hn/32, En), block (32, 8)
// ---------------------------------------------------------------------
__global__ void prep_w1t_kernel(const float* __restrict__ ex_ln_g,
                                const float* __restrict__ ex_ln_b,
                                const float* __restrict__ ex_w1) {
    __shared__ float s[32][33];
    __shared__ float sg[32];
    const int e = blockIdx.z;
    const int d0 = blockIdx.x * 32, h0 = blockIdx.y * 32;
    const int tx = threadIdx.x, ty = threadIdx.y;

    if (ty == 0) sg[tx] = ex_ln_g[e * Dn + d0 + tx];

    const float* W = ex_w1 + (size_t)e * Dn * Hn;
    float bacc = 0.0f;
#pragma unroll
    for (int r = 0; r < 4; r++) {
        int dl = ty * 4 + r;
        int d = d0 + dl;
        float w = W[(size_t)d * Hn + h0 + tx];
        s[dl][tx] = w;
        bacc = fmaf(ex_ln_b[e * Dn + d], w, bacc);
    }
    atomicAdd(&g_b1p[e * Hn + h0 + tx], bacc);
    __syncthreads();

#pragma unroll
    for (int r = 0; r < 4; r++) {
        int hl = ty * 4 + r;
        float v = s[tx][hl] * sg[tx];   // w1[d0+tx][h0+hl] * ln_g[d0+tx]
        __nv_bfloat16 hi = __float2bfloat16(v);
        __nv_bfloat16 lo = __float2bfloat16(v - __bfloat162float(hi));
        size_t off = ((size_t)e * Hn + h0 + hl) * Dn + d0 + tx;
        g_w1t_hi[off] = hi;
        g_w1t_lo[off] = lo;
    }
}

// ---------------------------------------------------------------------
// Kernel 2: per-row normalize (-> bf16 hi/lo) + gate logits + softmax
// grid: Bn blocks, 256 threads
// ---------------------------------------------------------------------
__global__ void norm_gate_kernel(const float* __restrict__ x,
                                 const float* __restrict__ gln_g,
                                 const float* __restrict__ gln_b,
                                 const float* __restrict__ gate_w,
                                 const float* __restrict__ gate_b) {
    int row = blockIdx.x;
    int t = threadIdx.x;
    int lid = t & 31, wid = t >> 5;

    float4 v = ((const float4*)(x + (size_t)row * Dn))[t];
    float xv[4] = {v.x, v.y, v.z, v.w};
    float s = xv[0] + xv[1] + xv[2] + xv[3];
    float ss = xv[0]*xv[0] + xv[1]*xv[1] + xv[2]*xv[2] + xv[3]*xv[3];

#pragma unroll
    for (int o = 16; o > 0; o >>= 1) {
        s  += __shfl_down_sync(0xffffffffu, s,  o);
        ss += __shfl_down_sync(0xffffffffu, ss, o);
    }
    __shared__ float red0[8], red1[8];
    if (lid == 0) { red0[wid] = s; red1[wid] = ss; }
    __syncthreads();
    __shared__ float s_mean, s_rstd;
    if (t == 0) {
        float a = 0.0f, b2 = 0.0f;
#pragma unroll
        for (int i = 0; i < 8; i++) { a += red0[i]; b2 += red1[i]; }
        float m = a * (1.0f / Dn);
        float var = b2 * (1.0f / Dn) - m * m;
        s_mean = m;
        s_rstd = rsqrtf(var + EPSv);
    }
    __syncthreads();
    float m = s_mean, r = s_rstd;

    float nn[4];
    __nv_bfloat16 hhi[4], hlo[4];
#pragma unroll
    for (int i = 0; i < 4; i++) {
        nn[i] = (xv[i] - m) * r;
        hhi[i] = __float2bfloat16(nn[i]);
        hlo[i] = __float2bfloat16(nn[i] - __bfloat162float(hhi[i]));
    }
    *(uint2*)(g_ahi + (size_t)row * Dn + t * 4) = *(uint2*)hhi;
    *(uint2*)(g_alo + (size_t)row * Dn + t * 4) = *(uint2*)hlo;

    // gate: (normed*g + b) @ gate_w
    float gl[4] = {0, 0, 0, 0};
    int d0 = t * 4;
#pragma unroll
    for (int i = 0; i < 4; i++) {
        int d = d0 + i;
        float tt = fmaf(nn[i], gln_g[d], gln_b[d]);
        float4 w4 = ((const float4*)gate_w)[d];
        gl[0] = fmaf(tt, w4.x, gl[0]);
        gl[1] = fmaf(tt, w4.y, gl[1]);
        gl[2] = fmaf(tt, w4.z, gl[2]);
        gl[3] = fmaf(tt, w4.w, gl[3]);
    }
#pragma unroll
    for (int e = 0; e < 4; e++)
#pragma unroll
        for (int o = 16; o > 0; o >>= 1)
            gl[e] += __shfl_down_sync(0xffffffffu, gl[e], o);

    __shared__ float gred[8][4];
    if (lid == 0)
#pragma unroll
        for (int e = 0; e < 4; e++) gred[wid][e] = gl[e];
    __syncthreads();
    if (t == 0) {
        float lg[4];
#pragma unroll
        for (int e = 0; e < 4; e++) {
            float a = gate_b[e];
#pragma unroll
            for (int w = 0; w < 8; w++) a += gred[w][e];
            lg[e] = a;
        }
        float mx = fmaxf(fmaxf(lg[0], lg[1]), fmaxf(lg[2], lg[3]));
        float ex[4], den = 0.0f;
#pragma unroll
        for (int e = 0; e < 4; e++) { ex[e] = expf(lg[e] - mx); den += ex[e]; }
        float inv = 1.0f / den;
#pragma unroll
        for (int e = 0; e < 4; e++) g_gw[row * 4 + e] = ex[e] * inv;
    }
}

// ---------------------------------------------------------------------
// Kernel 3: bf16-split GEMM via mma.sync (HMMA), cp.async 4-stage pipeline.
//   D = Ahi*Bhi + Ahi*Blo + Alo*Bhi  (fp32 accum), fused +b1, exact GELU,
//   project to C=3, reduce in smem, one global atomic per (row,c).
// grid: (Hn/BN=16, Bn/BM=128, En=4), 256 threads (8 warps: 2m x 4n).
// ---------------------------------------------------------------------
__global__ void __launch_bounds__(256, 1)
moe_gemm_tc_kernel(const float* __restrict__ ex_w2) {
    extern __shared__ char smem[];
    const uint32_t sbase = smem_u32(smem);
    float* sacc = (float*)(smem + EXT_OFF);              // [128][3]
    float* b1s  = (float*)(smem + EXT_OFF + 1536);       // [128]
    float* w2s  = (float*)(smem + EXT_OFF + 1536 + 512); // [128][3]

    const int t = threadIdx.x;
    const int e  = blockIdx.z;
    const int n0 = blockIdx.x * BN;
    const int m0 = blockIdx.y * BM;
    const int l = t & 31, wid = t >> 5;
    const int wm = wid >> 2, wn = wid & 3;

    if (t < 128) b1s[t] = g_b1p[e * Hn + n0 + t];
    for (int i = t; i < 384; i += 256) {
        w2s[i] = ex_w2[((size_t)e * Hn + n0 + i / 3) * Cn + (i % 3)];
        sacc[i] = 0.0f;
    }

    const __nv_bfloat16* Ahg = g_ahi + (size_t)m0 * Dn;
    const __nv_bfloat16* Alg = g_alo + (size_t)m0 * Dn;
    const __nv_bfloat16* Bhg = g_w1t_hi + ((size_t)e * Hn + n0) * Dn;
    const __nv_bfloat16* Blg = g_w1t_lo + ((size_t)e * Hn + n0) * Dn;

    // per-thread stage-load geometry: 2 segs/tile, 4 tiles -> 8 cp16/thread
    const int ld_row0 = t >> 2;          // rows t/4 and t/4+64
    const int ld_seg  = t & 3;

    auto load_stage = [&](int kt) {
        const uint32_t sb = sbase + (uint32_t)(kt & (NSTG - 1)) * STAGE_B;
        const int k0 = kt * BK;
#pragma unroll
        for (int i = 0; i < 2; i++) {
            const int row = ld_row0 + i * 64;
            const uint32_t so = (uint32_t)row * ROWB + ld_seg * 16;
            const size_t go = (size_t)row * Dn + k0 + ld_seg * 8;
            cp16(sb + so,              Ahg + go);
            cp16(sb + TILE_B + so,     Alg + go);
            cp16(sb + 2 * TILE_B + so, Bhg + go);
            cp16(sb + 3 * TILE_B + so, Blg + go);
        }
        CP_COMMIT();
    };

    float acc[4][4][4];
#pragma unroll
    for (int mi = 0; mi < 4; mi++)
#pragma unroll
        for (int ni = 0; ni < 4; ni++)
#pragma unroll
            for (int k = 0; k < 4; k++) acc[mi][ni][k] = 0.0f;

    load_stage(0);
    load_stage(1);
    load_stage(2);

    const uint32_t o_lane = (uint32_t)(l & 15) * ROWB + (uint32_t)(l >> 4) * 16;
    const int NT = Dn / BK;   // 32

    for (int kt = 0; kt < NT; kt++) {
        if (kt < NT - 2)      asm volatile("cp.async.wait_group 2;" ::: "memory");
        else if (kt == NT - 2) asm volatile("cp.async.wait_group 1;" ::: "memory");
        else                   asm volatile("cp.async.wait_group 0;" ::: "memory");
        __syncthreads();
        if (kt + 3 < NT) load_stage(kt + 3);

        const uint32_t sb = sbase + (uint32_t)(kt & (NSTG - 1)) * STAGE_B;
        const uint32_t a_base = sb + (uint32_t)(wm * 64) * ROWB + o_lane;
        const uint32_t b_base = sb + 2 * TILE_B + (uint32_t)(wn * 32) * ROWB + o_lane;

#pragma unroll
        for (int ks = 0; ks < 2; ks++) {
            uint32_t ah[4][4], al[4][4], bh[4][2], bl[4][2];
#pragma unroll
            for (int mi = 0; mi < 4; mi++) {
                ldsm4(ah[mi], a_base + (uint32_t)(mi * 16) * ROWB + ks * 32);
                ldsm4(al[mi], a_base + TILE_B + (uint32_t)(mi * 16) * ROWB + ks * 32);
            }
#pragma unroll
            for (int pr = 0; pr < 2; pr++) {
                uint32_t r[4];
                ldsm4(r, b_base + (uint32_t)(pr * 16) * ROWB + ks * 32);
                bh[pr * 2][0] = r[0]; bh[pr * 2 + 1][0] = r[1];
                bh[pr * 2][1] = r[2]; bh[pr * 2 + 1][1] = r[3];
                ldsm4(r, b_base + TILE_B + (uint32_t)(pr * 16) * ROWB + ks * 32);
                bl[pr * 2][0] = r[0]; bl[pr * 2 + 1][0] = r[1];
                bl[pr * 2][1] = r[2]; bl[pr * 2 + 1][1] = r[3];
            }
#pragma unroll
            for (int mi = 0; mi < 4; mi++)
#pragma unroll
                for (int ni = 0; ni < 4; ni++) {
                    mma16816(acc[mi][ni], ah[mi], bh[ni]);
                    mma16816(acc[mi][ni], ah[mi], bl[ni]);
                    mma16816(acc[mi][ni], al[mi], bh[ni]);
                }
        }
    }

    // ---- epilogue ----
#pragma unroll
    for (int mi = 0; mi < 4; mi++) {
        const int r0 = wm * 64 + mi * 16 + (l >> 2);   // second row = r0 + 8
        float p0[3] = {0, 0, 0}, p1[3] = {0, 0, 0};
#pragma unroll
        for (int ni = 0; ni < 4; ni++) {
#pragma unroll
            for (int e2 = 0; e2 < 2; e2++) {
                const int n = wn * 32 + ni * 8 + (l & 3) * 2 + e2;
                const float bz = b1s[n];
                float hv0 = acc[mi][ni][e2] + bz;
                float hv1 = acc[mi][ni][2 + e2] + bz;
                float g0 = 0.5f * hv0 * (1.0f + erff(hv0 * 0.70710678118654752f));
                float g1 = 0.5f * hv1 * (1.0f + erff(hv1 * 0.70710678118654752f));
#pragma unroll
                for (int c = 0; c < 3; c++) {
                    const float w = w2s[n * 3 + c];
                    p0[c] = fmaf(g0, w, p0[c]);
                    p1[c] = fmaf(g1, w, p1[c]);
                }
            }
        }
#pragma unroll
        for (int c = 0; c < 3; c++) {
            p0[c] += __shfl_xor_sync(0xffffffffu, p0[c], 1);
            p0[c] += __shfl_xor_sync(0xffffffffu, p0[c], 2);
            p1[c] += __shfl_xor_sync(0xffffffffu, p1[c], 1);
            p1[c] += __shfl_xor_sync(0xffffffffu, p1[c], 2);
        }
        if ((l & 3) == 0) {
#pragma unroll
            for (int c = 0; c < 3; c++) {
                atomicAdd(&sacc[r0 * 3 + c], p0[c]);
                atomicAdd(&sacc[(r0 + 8) * 3 + c], p1[c]);
            }
        }
    }
    __syncthreads();

    for (int i = t; i < 384; i += 256) {
        const int row = i / 3, c = i % 3;
        atomicAdd(&g_acc[((size_t)e * Bn + m0 + row) * Cn + c], sacc[i]);
    }
}

// ---------------------------------------------------------------------
// Kernel 4: out[b,c] = sum_e gw[b,e] * (acc[e,b,c] + b2[e,c])
// ---------------------------------------------------------------------
__global__ void finalize_kernel(const float* __restrict__ ex_b2,
                                float* __restrict__ out) {
    int idx = blockIdx.x * 256 + threadIdx.x;
    if (idx >= Bn * Cn) return;
    int b = idx / Cn, c = idx % Cn;
    float s = 0.0f;
#pragma unroll
    for (int e = 0; e < En; e++) {
        float logit = g_acc[((size_t)e * Bn + b) * Cn + c] + ex_b2[e * Cn + c];
        s = fmaf(g_gw[b * En + e], logit, s);
    }
    out[idx] = s;
}

// ---------------------------------------------------------------------
extern "C" void kernel_launch(void* const* d_in, const int* in_sizes, int n_in,
                              void* d_out, int out_size) {
    const float* x         = (const float*)d_in[0];
    const float* gate_ln_g = (const float*)d_in[1];
    const float* gate_ln_b = (const float*)d_in[2];
    const float* gate_w    = (const float*)d_in[3];
    const float* gate_b    = (const float*)d_in[4];
    const float* ex_ln_g   = (const float*)d_in[5];
    const float* ex_ln_b   = (const float*)d_in[6];
    const float* ex_w1     = (const float*)d_in[7];
    const float* ex_b1     = (const float*)d_in[8];
    const float* ex_w2     = (const float*)d_in[9];
    const float* ex_b2     = (const float*)d_in[10];
    float* out = (float*)d_out;

    cudaFuncSetAttribute(moe_gemm_tc_kernel,
                         cudaFuncAttributeMaxDynamicSharedMemorySize, SMEM_TOTAL);

    init_kernel<<<(En * Bn * Cn + 255) / 256, 256>>>(ex_b1);
    prep_w1t_kernel<<<dim3(Dn / 32, Hn / 32, En), dim3(32, 8)>>>(ex_ln_g, ex_ln_b, ex_w1);
    norm_gate_kernel<<<Bn, 256>>>(x, gate_ln_g, gate_ln_b, gate_w, gate_b);
    moe_gemm_tc_kernel<<<dim3(Hn / BN, Bn / BM, En), 256, SMEM_TOTAL>>>(ex_w2);
    finalize_kernel<<<(Bn * Cn + 255) / 256, 256>>>(ex_b2, out);
}

// round 11
// speedup vs baseline: 2.1088x; 1.1438x over previous
#include <cuda_runtime.h>
#include <cuda_bf16.h>
#include <math.h>
#include <cstdint>

// Problem constants
#define Bn 16384
#define Dn 1024
#define Hn 2048
#define En 4
#define Cn 3
#define EPSv 1e-5f

// GEMM tiling (mma.sync path — base-ISA tensor cores; tcgen05 unavailable on
// this build's compute_103 lowering)
#define BM 128
#define BN 128
#define BK 32
#define NSTG 2                       // 2-stage double buffer -> 2 CTAs/SM
#define ROWB 80                      // 32 bf16 = 64B payload + 16B pad (conflict-free ldmatrix)
#define TILE_B (128 * ROWB)          // 10240 B per operand tile
#define STAGE_B (4 * TILE_B)         // Ahi, Alo, Bhi, Blo = 40960 B
#define EXT_OFF (NSTG * STAGE_B)     // 81920
#define SMEM_TOTAL (EXT_OFF + 1536 + 512 + 1536)   // +sacc +b1s +w2s = 85504

// -------- scratch (static device memory; no allocation allowed) --------
__device__ __nv_bfloat16 g_ahi[(size_t)Bn * Dn];            // 32 MB
__device__ __nv_bfloat16 g_alo[(size_t)Bn * Dn];            // 32 MB
__device__ __nv_bfloat16 g_w1t_hi[(size_t)En * Hn * Dn];    // 16 MB  [e][h][d]
__device__ __nv_bfloat16 g_w1t_lo[(size_t)En * Hn * Dn];    // 16 MB
__device__ float g_b1p[En * Hn];                            // folded bias
__device__ float g_gw[Bn * En];                             // softmax gate weights
__device__ float g_acc[(size_t)En * Bn * Cn];               // partial logits (pre-b2)

// ======================= helpers =========================
__device__ __forceinline__ uint32_t smem_u32(const void* p) {
    uint32_t a;
    asm("{ .reg .u64 t; cvta.to.shared.u64 t, %1; cvt.u32.u64 %0, t; }" : "=r"(a) : "l"(p));
    return a;
}

__device__ __forceinline__ void cp16(uint32_t dst, const void* src) {
    asm volatile("cp.async.cg.shared.global [%0], [%1], 16;" :: "r"(dst), "l"(src));
}
#define CP_COMMIT() asm volatile("cp.async.commit_group;" ::: "memory")

__device__ __forceinline__ void ldsm4(uint32_t* r, uint32_t addr) {
    asm volatile("ldmatrix.sync.aligned.m8n8.x4.shared.b16 {%0,%1,%2,%3}, [%4];"
                 : "=r"(r[0]), "=r"(r[1]), "=r"(r[2]), "=r"(r[3]) : "r"(addr));
}

__device__ __forceinline__ void mma16816(float* d, const uint32_t* a, const uint32_t* b) {
    asm volatile(
        "mma.sync.aligned.m16n8k16.row.col.f32.bf16.bf16.f32 "
        "{%0,%1,%2,%3}, {%4,%5,%6,%7}, {%8,%9}, {%0,%1,%2,%3};"
        : "+f"(d[0]), "+f"(d[1]), "+f"(d[2]), "+f"(d[3])
        : "r"(a[0]), "r"(a[1]), "r"(a[2]), "r"(a[3]), "r"(b[0]), "r"(b[1]));
}

// ---------------------------------------------------------------------
// Kernel 0: zero g_acc, init b1p = ex_b1
// ---------------------------------------------------------------------
__global__ void init_kernel(const float* __restrict__ ex_b1) {
    int i = blockIdx.x * 256 + threadIdx.x;
    if (i < En * Bn * Cn) g_acc[i] = 0.0f;
    if (i < En * Hn) g_b1p[i] = ex_b1[i];
}

// ---------------------------------------------------------------------
// Kernel 1: fold LN affine into W1, transpose to [e][h][d], split bf16 hi/lo.
//   Also accumulate b1p[e,h] += sum_d ln_b[e,d] * w1[e,d,h]  (atomic partials)
// grid: (Dn/32, Hn/32, En), block (32, 8)
// ---------------------------------------------------------------------
__global__ void prep_w1t_kernel(const float* __restrict__ ex_ln_g,
                                const float* __restrict__ ex_ln_b,
                                const float* __restrict__ ex_w1) {
    __shared__ float s[32][33];
    __shared__ float sg[32];
    const int e = blockIdx.z;
    const int d0 = blockIdx.x * 32, h0 = blockIdx.y * 32;
    const int tx = threadIdx.x, ty = threadIdx.y;

    if (ty == 0) sg[tx] = ex_ln_g[e * Dn + d0 + tx];

    const float* W = ex_w1 + (size_t)e * Dn * Hn;
    float bacc = 0.0f;
#pragma unroll
    for (int r = 0; r < 4; r++) {
        int dl = ty * 4 + r;
        int d = d0 + dl;
        float w = W[(size_t)d * Hn + h0 + tx];
        s[dl][tx] = w;
        bacc = fmaf(ex_ln_b[e * Dn + d], w, bacc);
    }
    atomicAdd(&g_b1p[e * Hn + h0 + tx], bacc);
    __syncthreads();

#pragma unroll
    for (int r = 0; r < 4; r++) {
        int hl = ty * 4 + r;
        float v = s[tx][hl] * sg[tx];   // w1[d0+tx][h0+hl] * ln_g[d0+tx]
        __nv_bfloat16 hi = __float2bfloat16(v);
        __nv_bfloat16 lo = __float2bfloat16(v - __bfloat162float(hi));
        size_t off = ((size_t)e * Hn + h0 + hl) * Dn + d0 + tx;
        g_w1t_hi[off] = hi;
        g_w1t_lo[off] = lo;
    }
}

// ---------------------------------------------------------------------
// Kernel 2: per-row normalize (-> bf16 hi/lo) + gate logits + softmax
// grid: Bn blocks, 256 threads
// ---------------------------------------------------------------------
__global__ void norm_gate_kernel(const float* __restrict__ x,
                                 const float* __restrict__ gln_g,
                                 const float* __restrict__ gln_b,
                                 const float* __restrict__ gate_w,
                                 const float* __restrict__ gate_b) {
    int row = blockIdx.x;
    int t = threadIdx.x;
    int lid = t & 31, wid = t >> 5;

    float4 v = ((const float4*)(x + (size_t)row * Dn))[t];
    float xv[4] = {v.x, v.y, v.z, v.w};
    float s = xv[0] + xv[1] + xv[2] + xv[3];
    float ss = xv[0]*xv[0] + xv[1]*xv[1] + xv[2]*xv[2] + xv[3]*xv[3];

#pragma unroll
    for (int o = 16; o > 0; o >>= 1) {
        s  += __shfl_down_sync(0xffffffffu, s,  o);
        ss += __shfl_down_sync(0xffffffffu, ss, o);
    }
    __shared__ float red0[8], red1[8];
    if (lid == 0) { red0[wid] = s; red1[wid] = ss; }
    __syncthreads();
    __shared__ float s_mean, s_rstd;
    if (t == 0) {
        float a = 0.0f, b2 = 0.0f;
#pragma unroll
        for (int i = 0; i < 8; i++) { a += red0[i]; b2 += red1[i]; }
        float m = a * (1.0f / Dn);
        float var = b2 * (1.0f / Dn) - m * m;
        s_mean = m;
        s_rstd = rsqrtf(var + EPSv);
    }
    __syncthreads();
    float m = s_mean, r = s_rstd;

    float nn[4];
    __nv_bfloat16 hhi[4], hlo[4];
#pragma unroll
    for (int i = 0; i < 4; i++) {
        nn[i] = (xv[i] - m) * r;
        hhi[i] = __float2bfloat16(nn[i]);
        hlo[i] = __float2bfloat16(nn[i] - __bfloat162float(hhi[i]));
    }
    *(uint2*)(g_ahi + (size_t)row * Dn + t * 4) = *(uint2*)hhi;
    *(uint2*)(g_alo + (size_t)row * Dn + t * 4) = *(uint2*)hlo;

    // gate: (normed*g + b) @ gate_w
    float gl[4] = {0, 0, 0, 0};
    int d0 = t * 4;
#pragma unroll
    for (int i = 0; i < 4; i++) {
        int d = d0 + i;
        float tt = fmaf(nn[i], gln_g[d], gln_b[d]);
        float4 w4 = ((const float4*)gate_w)[d];
        gl[0] = fmaf(tt, w4.x, gl[0]);
        gl[1] = fmaf(tt, w4.y, gl[1]);
        gl[2] = fmaf(tt, w4.z, gl[2]);
        gl[3] = fmaf(tt, w4.w, gl[3]);
    }
#pragma unroll
    for (int e = 0; e < 4; e++)
#pragma unroll
        for (int o = 16; o > 0; o >>= 1)
            gl[e] += __shfl_down_sync(0xffffffffu, gl[e], o);

    __shared__ float gred[8][4];
    if (lid == 0)
#pragma unroll
        for (int e = 0; e < 4; e++) gred[wid][e] = gl[e];
    __syncthreads();
    if (t == 0) {
        float lg[4];
#pragma unroll
        for (int e = 0; e < 4; e++) {
            float a = gate_b[e];
#pragma unroll
            for (int w = 0; w < 8; w++) a += gred[w][e];
            lg[e] = a;
        }
        float mx = fmaxf(fmaxf(lg[0], lg[1]), fmaxf(lg[2], lg[3]));
        float ex[4], den = 0.0f;
#pragma unroll
        for (int e = 0; e < 4; e++) { ex[e] = expf(lg[e] - mx); den += ex[e]; }
        float inv = 1.0f / den;
#pragma unroll
        for (int e = 0; e < 4; e++) g_gw[row * 4 + e] = ex[e] * inv;
    }
}

// ---------------------------------------------------------------------
// Kernel 3: bf16-split GEMM via mma.sync (HMMA), 2-stage cp.async pipeline,
//   2 CTAs/SM for tensor-pipe overlap.
//   D = Ahi*Bhi + Ahi*Blo + Alo*Bhi  (fp32 accum), fused +b1, exact GELU,
//   project to C=3, reduce in smem, one global atomic per (row,c).
// grid: (Hn/BN=16, Bn/BM=128, En=4), 256 threads (8 warps: 2m x 4n).
// ---------------------------------------------------------------------
__global__ void __launch_bounds__(256, 2)
moe_gemm_tc_kernel(const float* __restrict__ ex_w2) {
    extern __shared__ char smem[];
    const uint32_t sbase = smem_u32(smem);
    float* sacc = (float*)(smem + EXT_OFF);              // [128][3]
    float* b1s  = (float*)(smem + EXT_OFF + 1536);       // [128]
    float* w2s  = (float*)(smem + EXT_OFF + 1536 + 512); // [128][3]

    const int t = threadIdx.x;
    const int e  = blockIdx.z;
    const int n0 = blockIdx.x * BN;
    const int m0 = blockIdx.y * BM;
    const int l = t & 31, wid = t >> 5;
    const int wm = wid >> 2, wn = wid & 3;

    if (t < 128) b1s[t] = g_b1p[e * Hn + n0 + t];
    for (int i = t; i < 384; i += 256) {
        w2s[i] = ex_w2[((size_t)e * Hn + n0 + i / 3) * Cn + (i % 3)];
        sacc[i] = 0.0f;
    }

    const __nv_bfloat16* Ahg = g_ahi + (size_t)m0 * Dn;
    const __nv_bfloat16* Alg = g_alo + (size_t)m0 * Dn;
    const __nv_bfloat16* Bhg = g_w1t_hi + ((size_t)e * Hn + n0) * Dn;
    const __nv_bfloat16* Blg = g_w1t_lo + ((size_t)e * Hn + n0) * Dn;

    // per-thread stage-load geometry: 2 segs/tile, 4 tiles -> 8 cp16/thread
    const int ld_row0 = t >> 2;          // rows t/4 and t/4+64
    const int ld_seg  = t & 3;

    auto load_stage = [&](int kt) {
        const uint32_t sb = sbase + (uint32_t)(kt & (NSTG - 1)) * STAGE_B;
        const int k0 = kt * BK;
#pragma unroll
        for (int i = 0; i < 2; i++) {
            const int row = ld_row0 + i * 64;
            const uint32_t so = (uint32_t)row * ROWB + ld_seg * 16;
            const size_t go = (size_t)row * Dn + k0 + ld_seg * 8;
            cp16(sb + so,              Ahg + go);
            cp16(sb + TILE_B + so,     Alg + go);
            cp16(sb + 2 * TILE_B + so, Bhg + go);
            cp16(sb + 3 * TILE_B + so, Blg + go);
        }
        CP_COMMIT();
    };

    float acc[4][4][4];
#pragma unroll
    for (int mi = 0; mi < 4; mi++)
#pragma unroll
        for (int ni = 0; ni < 4; ni++)
#pragma unroll
            for (int k = 0; k < 4; k++) acc[mi][ni][k] = 0.0f;

    load_stage(0);
    load_stage(1);

    const uint32_t o_lane = (uint32_t)(l & 15) * ROWB + (uint32_t)(l >> 4) * 16;
    const int NT = Dn / BK;   // 32

    for (int kt = 0; kt < NT; kt++) {
        if (kt < NT - 1) asm volatile("cp.async.wait_group 1;" ::: "memory");
        else             asm volatile("cp.async.wait_group 0;" ::: "memory");
        __syncthreads();   // publish stage kt to all warps

        const uint32_t sb = sbase + (uint32_t)(kt & (NSTG - 1)) * STAGE_B;
        const uint32_t a_base = sb + (uint32_t)(wm * 64) * ROWB + o_lane;
        const uint32_t b_base = sb + 2 * TILE_B + (uint32_t)(wn * 32) * ROWB + o_lane;

#pragma unroll
        for (int ks = 0; ks < 2; ks++) {
            uint32_t ah[4][4], al[4][4], bh[4][2], bl[4][2];
#pragma unroll
            for (int mi = 0; mi < 4; mi++) {
                ldsm4(ah[mi], a_base + (uint32_t)(mi * 16) * ROWB + ks * 32);
                ldsm4(al[mi], a_base + TILE_B + (uint32_t)(mi * 16) * ROWB + ks * 32);
            }
#pragma unroll
            for (int pr = 0; pr < 2; pr++) {
                uint32_t r[4];
                ldsm4(r, b_base + (uint32_t)(pr * 16) * ROWB + ks * 32);
                bh[pr * 2][0] = r[0]; bh[pr * 2 + 1][0] = r[1];
                bh[pr * 2][1] = r[2]; bh[pr * 2 + 1][1] = r[3];
                ldsm4(r, b_base + TILE_B + (uint32_t)(pr * 16) * ROWB + ks * 32);
                bl[pr * 2][0] = r[0]; bl[pr * 2 + 1][0] = r[1];
                bl[pr * 2][1] = r[2]; bl[pr * 2 + 1][1] = r[3];
            }
#pragma unroll
            for (int mi = 0; mi < 4; mi++)
#pragma unroll
                for (int ni = 0; ni < 4; ni++) {
                    mma16816(acc[mi][ni], ah[mi], bh[ni]);
                    mma16816(acc[mi][ni], ah[mi], bl[ni]);
                    mma16816(acc[mi][ni], al[mi], bh[ni]);
                }
        }

        __syncthreads();   // all warps done reading buf (kt&1) before overwrite
        if (kt + 2 < NT) load_stage(kt + 2);
    }

    // ---- epilogue ----
#pragma unroll
    for (int mi = 0; mi < 4; mi++) {
        const int r0 = wm * 64 + mi * 16 + (l >> 2);   // second row = r0 + 8
        float p0[3] = {0, 0, 0}, p1[3] = {0, 0, 0};
#pragma unroll
        for (int ni = 0; ni < 4; ni++) {
#pragma unroll
            for (int e2 = 0; e2 < 2; e2++) {
                const int n = wn * 32 + ni * 8 + (l & 3) * 2 + e2;
                const float bz = b1s[n];
                float hv0 = acc[mi][ni][e2] + bz;
                float hv1 = acc[mi][ni][2 + e2] + bz;
                float g0 = 0.5f * hv0 * (1.0f + erff(hv0 * 0.70710678118654752f));
                float g1 = 0.5f * hv1 * (1.0f + erff(hv1 * 0.70710678118654752f));
#pragma unroll
                for (int c = 0; c < 3; c++) {
                    const float w = w2s[n * 3 + c];
                    p0[c] = fmaf(g0, w, p0[c]);
                    p1[c] = fmaf(g1, w, p1[c]);
                }
            }
        }
#pragma unroll
        for (int c = 0; c < 3; c++) {
            p0[c] += __shfl_xor_sync(0xffffffffu, p0[c], 1);
            p0[c] += __shfl_xor_sync(0xffffffffu, p0[c], 2);
            p1[c] += __shfl_xor_sync(0xffffffffu, p1[c], 1);
            p1[c] += __shfl_xor_sync(0xffffffffu, p1[c], 2);
        }
        if ((l & 3) == 0) {
#pragma unroll
            for (int c = 0; c < 3; c++) {
                atomicAdd(&sacc[r0 * 3 + c], p0[c]);
                atomicAdd(&sacc[(r0 + 8) * 3 + c], p1[c]);
            }
        }
    }
    __syncthreads();

    for (int i = t; i < 384; i += 256) {
        const int row = i / 3, c = i % 3;
        atomicAdd(&g_acc[((size_t)e * Bn + m0 + row) * Cn + c], sacc[i]);
    }
}

// ---------------------------------------------------------------------
// Kernel 4: out[b,c] = sum_e gw[b,e] * (acc[e,b,c] + b2[e,c])
// ---------------------------------------------------------------------
__global__ void finalize_kernel(const float* __restrict__ ex_b2,
                                float* __restrict__ out) {
    int idx = blockIdx.x * 256 + threadIdx.x;
    if (idx >= Bn * Cn) return;
    int b = idx / Cn, c = idx % Cn;
    float s = 0.0f;
#pragma unroll
    for (int e = 0; e < En; e++) {
        float logit = g_acc[((size_t)e * Bn + b) * Cn + c] + ex_b2[e * Cn + c];
        s = fmaf(g_gw[b * En + e], logit, s);
    }
    out[idx] = s;
}

// ---------------------------------------------------------------------
extern "C" void kernel_launch(void* const* d_in, const int* in_sizes, int n_in,
                              void* d_out, int out_size) {
    const float* x         = (const float*)d_in[0];
    const float* gate_ln_g = (const float*)d_in[1];
    const float* gate_ln_b = (const float*)d_in[2];
    const float* gate_w    = (const float*)d_in[3];
    const float* gate_b    = (const float*)d_in[4];
    const float* ex_ln_g   = (const float*)d_in[5];
    const float* ex_ln_b   = (const float*)d_in[6];
    const float* ex_w1     = (const float*)d_in[7];
    const float* ex_b1     = (const float*)d_in[8];
    const float* ex_w2     = (const float*)d_in[9];
    const float* ex_b2     = (const float*)d_in[10];
    float* out = (float*)d_out;

    cudaFuncSetAttribute(moe_gemm_tc_kernel,
                         cudaFuncAttributeMaxDynamicSharedMemorySize, SMEM_TOTAL);

    init_kernel<<<(En * Bn * Cn + 255) / 256, 256>>>(ex_b1);
    prep_w1t_kernel<<<dim3(Dn / 32, Hn / 32, En), dim3(32, 8)>>>(ex_ln_g, ex_ln_b, ex_w1);
    norm_gate_kernel<<<Bn, 256>>>(x, gate_ln_g, gate_ln_b, gate_w, gate_b);
    moe_gemm_tc_kernel<<<dim3(Hn / BN, Bn / BM, En), 256, SMEM_TOTAL>>>(ex_w2);
    finalize_kernel<<<(Bn * Cn + 255) / 256, 256>>>(ex_b2, out);
}

// round 14
// speedup vs baseline: 2.4439x; 1.1589x over previous
#include <cuda_runtime.h>
#include <cuda_bf16.h>
#include <math.h>
#include <cstdint>

// Problem constants
#define Bn 16384
#define Dn 1024
#define Hn 2048
#define En 4
#define Cn 3
#define EPSv 1e-5f

// GEMM tiling (mma.sync path — base-ISA tensor cores; tcgen05 unavailable on
// this build's compute_103 lowering)
#define BM 128
#define BN 128
#define BK 32
#define NSTG 3                       // 3-stage ring -> single barrier per k-tile
#define ROWB 64                      // 32 bf16 = 64B, XOR-swizzled (no pad)
#define TILE_B (128 * ROWB)          // 8192 B per operand tile
#define STAGE_B (4 * TILE_B)         // Ahi, Alo, Bhi, Blo = 32768 B
#define EXT_OFF (NSTG * STAGE_B)     // 98304
#define SMEM_TOTAL (EXT_OFF + 1536 + 512 + 1536)   // 101888 -> 2 CTAs/SM

// -------- scratch (static device memory; no allocation allowed) --------
__device__ __nv_bfloat16 g_ahi[(size_t)Bn * Dn];            // 32 MB
__device__ __nv_bfloat16 g_alo[(size_t)Bn * Dn];            // 32 MB
__device__ __nv_bfloat16 g_w1t_hi[(size_t)En * Hn * Dn];    // 16 MB  [e][h][d]
__device__ __nv_bfloat16 g_w1t_lo[(size_t)En * Hn * Dn];    // 16 MB
__device__ float g_b1p[En * Hn];                            // folded bias
__device__ float g_gw[Bn * En];                             // softmax gate weights
__device__ float g_acc[(size_t)En * Bn * Cn];               // partial logits (pre-b2)

// ======================= helpers =========================
__device__ __forceinline__ uint32_t smem_u32(const void* p) {
    uint32_t a;
    asm("{ .reg .u64 t; cvta.to.shared.u64 t, %1; cvt.u32.u64 %0, t; }" : "=r"(a) : "l"(p));
    return a;
}

__device__ __forceinline__ void cp16(uint32_t dst, const void* src) {
    asm volatile("cp.async.cg.shared.global [%0], [%1], 16;" :: "r"(dst), "l"(src));
}
#define CP_COMMIT() asm volatile("cp.async.commit_group;" ::: "memory")

__device__ __forceinline__ void ldsm4(uint32_t* r, uint32_t addr) {
    asm volatile("ldmatrix.sync.aligned.m8n8.x4.shared.b16 {%0,%1,%2,%3}, [%4];"
                 : "=r"(r[0]), "=r"(r[1]), "=r"(r[2]), "=r"(r[3]) : "r"(addr));
}

__device__ __forceinline__ void mma16816(float* d, const uint32_t* a, const uint32_t* b) {
    asm volatile(
        "mma.sync.aligned.m16n8k16.row.col.f32.bf16.bf16.f32 "
        "{%0,%1,%2,%3}, {%4,%5,%6,%7}, {%8,%9}, {%0,%1,%2,%3};"
        : "+f"(d[0]), "+f"(d[1]), "+f"(d[2]), "+f"(d[3])
        : "r"(a[0]), "r"(a[1]), "r"(a[2]), "r"(a[3]), "r"(b[0]), "r"(b[1]));
}

// ---------------------------------------------------------------------
// Kernel 0: zero g_acc, init b1p = ex_b1
// ---------------------------------------------------------------------
__global__ void init_kernel(const float* __restrict__ ex_b1) {
    int i = blockIdx.x * 256 + threadIdx.x;
    if (i < En * Bn * Cn) g_acc[i] = 0.0f;
    if (i < En * Hn) g_b1p[i] = ex_b1[i];
}

// ---------------------------------------------------------------------
// Kernel 1: fold LN affine into W1, transpose to [e][h][d], split bf16 hi/lo.
//   Also accumulate b1p[e,h] += sum_d ln_b[e,d] * w1[e,d,h]  (atomic partials)
// grid: (Dn/32, Hn/32, En), block (32, 8)
// ---------------------------------------------------------------------
__global__ void prep_w1t_kernel(const float* __restrict__ ex_ln_g,
                                const float* __restrict__ ex_ln_b,
                                const float* __restrict__ ex_w1) {
    __shared__ float s[32][33];
    __shared__ float sg[32];
    const int e = blockIdx.z;
    const int d0 = blockIdx.x * 32, h0 = blockIdx.y * 32;
    const int tx = threadIdx.x, ty = threadIdx.y;

    if (ty == 0) sg[tx] = ex_ln_g[e * Dn + d0 + tx];

    const float* W = ex_w1 + (size_t)e * Dn * Hn;
    float bacc = 0.0f;
#pragma unroll
    for (int r = 0; r < 4; r++) {
        int dl = ty * 4 + r;
        int d = d0 + dl;
        float w = W[(size_t)d * Hn + h0 + tx];
        s[dl][tx] = w;
        bacc = fmaf(ex_ln_b[e * Dn + d], w, bacc);
    }
    atomicAdd(&g_b1p[e * Hn + h0 + tx], bacc);
    __syncthreads();

#pragma unroll
    for (int r = 0; r < 4; r++) {
        int hl = ty * 4 + r;
        float v = s[tx][hl] * sg[tx];   // w1[d0+tx][h0+hl] * ln_g[d0+tx]
        __nv_bfloat16 hi = __float2bfloat16(v);
        __nv_bfloat16 lo = __float2bfloat16(v - __bfloat162float(hi));
        size_t off = ((size_t)e * Hn + h0 + hl) * Dn + d0 + tx;
        g_w1t_hi[off] = hi;
        g_w1t_lo[off] = lo;
    }
}

// ---------------------------------------------------------------------
// Kernel 2: per-row normalize (-> bf16 hi/lo) + gate logits + softmax
// grid: Bn blocks, 256 threads
// ---------------------------------------------------------------------
__global__ void norm_gate_kernel(const float* __restrict__ x,
                                 const float* __restrict__ gln_g,
                                 const float* __restrict__ gln_b,
                                 const float* __restrict__ gate_w,
                                 const float* __restrict__ gate_b) {
    int row = blockIdx.x;
    int t = threadIdx.x;
    int lid = t & 31, wid = t >> 5;

    float4 v = ((const float4*)(x + (size_t)row * Dn))[t];
    float xv[4] = {v.x, v.y, v.z, v.w};
    float s = xv[0] + xv[1] + xv[2] + xv[3];
    float ss = xv[0]*xv[0] + xv[1]*xv[1] + xv[2]*xv[2] + xv[3]*xv[3];

#pragma unroll
    for (int o = 16; o > 0; o >>= 1) {
        s  += __shfl_down_sync(0xffffffffu, s,  o);
        ss += __shfl_down_sync(0xffffffffu, ss, o);
    }
    __shared__ float red0[8], red1[8];
    if (lid == 0) { red0[wid] = s; red1[wid] = ss; }
    __syncthreads();
    __shared__ float s_mean, s_rstd;
    if (t == 0) {
        float a = 0.0f, b2 = 0.0f;
#pragma unroll
        for (int i = 0; i < 8; i++) { a += red0[i]; b2 += red1[i]; }
        float m = a * (1.0f / Dn);
        float var = b2 * (1.0f / Dn) - m * m;
        s_mean = m;
        s_rstd = rsqrtf(var + EPSv);
    }
    __syncthreads();
    float m = s_mean, r = s_rstd;

    float nn[4];
    __nv_bfloat16 hhi[4], hlo[4];
#pragma unroll
    for (int i = 0; i < 4; i++) {
        nn[i] = (xv[i] - m) * r;
        hhi[i] = __float2bfloat16(nn[i]);
        hlo[i] = __float2bfloat16(nn[i] - __bfloat162float(hhi[i]));
    }
    *(uint2*)(g_ahi + (size_t)row * Dn + t * 4) = *(uint2*)hhi;
    *(uint2*)(g_alo + (size_t)row * Dn + t * 4) = *(uint2*)hlo;

    // gate: (normed*g + b) @ gate_w
    float gl[4] = {0, 0, 0, 0};
    int d0 = t * 4;
#pragma unroll
    for (int i = 0; i < 4; i++) {
        int d = d0 + i;
        float tt = fmaf(nn[i], gln_g[d], gln_b[d]);
        float4 w4 = ((const float4*)gate_w)[d];
        gl[0] = fmaf(tt, w4.x, gl[0]);
        gl[1] = fmaf(tt, w4.y, gl[1]);
        gl[2] = fmaf(tt, w4.z, gl[2]);
        gl[3] = fmaf(tt, w4.w, gl[3]);
    }
#pragma unroll
    for (int e = 0; e < 4; e++)
#pragma unroll
        for (int o = 16; o > 0; o >>= 1)
            gl[e] += __shfl_down_sync(0xffffffffu, gl[e], o);

    __shared__ float gred[8][4];
    if (lid == 0)
#pragma unroll
        for (int e = 0; e < 4; e++) gred[wid][e] = gl[e];
    __syncthreads();
    if (t == 0) {
        float lg[4];
#pragma unroll
        for (int e = 0; e < 4; e++) {
            float a = gate_b[e];
#pragma unroll
            for (int w = 0; w < 8; w++) a += gred[w][e];
            lg[e] = a;
        }
        float mx = fmaxf(fmaxf(lg[0], lg[1]), fmaxf(lg[2], lg[3]));
        float ex[4], den = 0.0f;
#pragma unroll
        for (int e = 0; e < 4; e++) { ex[e] = expf(lg[e] - mx); den += ex[e]; }
        float inv = 1.0f / den;
#pragma unroll
        for (int e = 0; e < 4; e++) g_gw[row * 4 + e] = ex[e] * inv;
    }
}

// ---------------------------------------------------------------------
// Kernel 3: bf16-split GEMM via mma.sync (HMMA), 3-stage cp.async ring,
//   one __syncthreads per k-tile, XOR-swizzled 64B rows, 2 CTAs/SM.
//   D = Ahi*Bhi + Ahi*Blo + Alo*Bhi  (fp32 accum), fused +b1, exact GELU,
//   project to C=3, reduce in smem, one global atomic per (row,c).
// grid: (Hn/BN=16, Bn/BM=128, En=4), 256 threads (8 warps: 2m x 4n).
// ---------------------------------------------------------------------
__global__ void __launch_bounds__(256, 2)
moe_gemm_tc_kernel(const float* __restrict__ ex_w2) {
    extern __shared__ char smem[];
    const uint32_t sbase = smem_u32(smem);
    float* sacc = (float*)(smem + EXT_OFF);              // [128][3]
    float* b1s  = (float*)(smem + EXT_OFF + 1536);       // [128]
    float* w2s  = (float*)(smem + EXT_OFF + 1536 + 512); // [128][3]

    const int t = threadIdx.x;
    const int e  = blockIdx.z;
    const int n0 = blockIdx.x * BN;
    const int m0 = blockIdx.y * BM;
    const int l = t & 31, wid = t >> 5;
    const int wm = wid >> 2, wn = wid & 3;

    if (t < 128) b1s[t] = g_b1p[e * Hn + n0 + t];
    for (int i = t; i < 384; i += 256) {
        w2s[i] = ex_w2[((size_t)e * Hn + n0 + i / 3) * Cn + (i % 3)];
        sacc[i] = 0.0f;
    }

    const __nv_bfloat16* Ahg = g_ahi + (size_t)m0 * Dn;
    const __nv_bfloat16* Alg = g_alo + (size_t)m0 * Dn;
    const __nv_bfloat16* Bhg = g_w1t_hi + ((size_t)e * Hn + n0) * Dn;
    const __nv_bfloat16* Blg = g_w1t_lo + ((size_t)e * Hn + n0) * Dn;

    // per-thread stage-load geometry: 2 segs/tile, 4 tiles -> 8 cp16/thread
    // phys seg = logical seg XOR ((row>>1)&3); row = t>>2 (+64) -> (t>>3)&3 invariant
    const int ld_row0 = t >> 2;
    const int ld_seg  = (t & 3) ^ ((t >> 3) & 3);

    auto load_stage = [&](int kt, int buf) {
        const uint32_t sb = sbase + (uint32_t)buf * STAGE_B;
        const int k0 = kt * BK;
#pragma unroll
        for (int i = 0; i < 2; i++) {
            const int row = ld_row0 + i * 64;
            const uint32_t so = (uint32_t)row * ROWB + ld_seg * 16;
            const size_t go = (size_t)row * Dn + k0 + (t & 3) * 8;
            cp16(sb + so,              Ahg + go);
            cp16(sb + TILE_B + so,     Alg + go);
            cp16(sb + 2 * TILE_B + so, Bhg + go);
            cp16(sb + 3 * TILE_B + so, Blg + go);
        }
        CP_COMMIT();
    };

    float acc[4][4][4];
#pragma unroll
    for (int mi = 0; mi < 4; mi++)
#pragma unroll
        for (int ni = 0; ni < 4; ni++)
#pragma unroll
            for (int k = 0; k < 4; k++) acc[mi][ni][k] = 0.0f;

    load_stage(0, 0);
    load_stage(1, 1);

    // ldmatrix lane offsets (per ks): row = l&15 (offsets are 16-multiples ->
    // swizzle term ((l&15)>>1)&3 invariant), seg = ks*2 + (l>>4)
    const int lswz = ((l & 15) >> 1) & 3;
    uint32_t o_lane[2];
#pragma unroll
    for (int ks = 0; ks < 2; ks++)
        o_lane[ks] = (uint32_t)(l & 15) * ROWB + (uint32_t)(((ks * 2 + (l >> 4)) ^ lswz) * 16);

    const int NT = Dn / BK;   // 32
    int buf = 0;              // buffer holding stage kt

    for (int kt = 0; kt < NT; kt++) {
        if (kt < NT - 1) asm volatile("cp.async.wait_group 1;" ::: "memory");
        else             asm volatile("cp.async.wait_group 0;" ::: "memory");
        __syncthreads();   // stage kt visible; all warps done with stage kt-1's buffer

        // prefetch stage kt+2 into the buffer freed by stage kt-1
        if (kt + 2 < NT) {
            int nbuf = buf + 2; if (nbuf >= NSTG) nbuf -= NSTG;
            load_stage(kt + 2, nbuf);
        }

        const uint32_t sb = sbase + (uint32_t)buf * STAGE_B;
        const uint32_t a_base0 = sb + (uint32_t)(wm * 64) * ROWB;
        const uint32_t b_base0 = sb + 2 * TILE_B + (uint32_t)(wn * 32) * ROWB;

#pragma unroll
        for (int ks = 0; ks < 2; ks++) {
            const uint32_t a_base = a_base0 + o_lane[ks];
            const uint32_t b_base = b_base0 + o_lane[ks];
            uint32_t ah[4][4], al[4][4], bh[4][2], bl[4][2];
#pragma unroll
            for (int mi = 0; mi < 4; mi++) {
                ldsm4(ah[mi], a_base + (uint32_t)(mi * 16) * ROWB);
                ldsm4(al[mi], a_base + TILE_B + (uint32_t)(mi * 16) * ROWB);
            }
#pragma unroll
            for (int pr = 0; pr < 2; pr++) {
                uint32_t r[4];
                ldsm4(r, b_base + (uint32_t)(pr * 16) * ROWB);
                bh[pr * 2][0] = r[0]; bh[pr * 2 + 1][0] = r[1];
                bh[pr * 2][1] = r[2]; bh[pr * 2 + 1][1] = r[3];
                ldsm4(r, b_base + TILE_B + (uint32_t)(pr * 16) * ROWB);
                bl[pr * 2][0] = r[0]; bl[pr * 2 + 1][0] = r[1];
                bl[pr * 2][1] = r[2]; bl[pr * 2 + 1][1] = r[3];
            }
#pragma unroll
            for (int mi = 0; mi < 4; mi++)
#pragma unroll
                for (int ni = 0; ni < 4; ni++) {
                    mma16816(acc[mi][ni], ah[mi], bh[ni]);
                    mma16816(acc[mi][ni], ah[mi], bl[ni]);
                    mma16816(acc[mi][ni], al[mi], bh[ni]);
                }
        }

        buf += 1; if (buf == NSTG) buf = 0;
    }

    // ---- epilogue ----
#pragma unroll
    for (int mi = 0; mi < 4; mi++) {
        const int r0 = wm * 64 + mi * 16 + (l >> 2);   // second row = r0 + 8
        float p0[3] = {0, 0, 0}, p1[3] = {0, 0, 0};
#pragma unroll
        for (int ni = 0; ni < 4; ni++) {
#pragma unroll
            for (int e2 = 0; e2 < 2; e2++) {
                const int n = wn * 32 + ni * 8 + (l & 3) * 2 + e2;
                const float bz = b1s[n];
                float hv0 = acc[mi][ni][e2] + bz;
                float hv1 = acc[mi][ni][2 + e2] + bz;
                float g0 = 0.5f * hv0 * (1.0f + erff(hv0 * 0.70710678118654752f));
                float g1 = 0.5f * hv1 * (1.0f + erff(hv1 * 0.70710678118654752f));
#pragma unroll
                for (int c = 0; c < 3; c++) {
                    const float w = w2s[n * 3 + c];
                    p0[c] = fmaf(g0, w, p0[c]);
                    p1[c] = fmaf(g1, w, p1[c]);
                }
            }
        }
#pragma unroll
        for (int c = 0; c < 3; c++) {
            p0[c] += __shfl_xor_sync(0xffffffffu, p0[c], 1);
            p0[c] += __shfl_xor_sync(0xffffffffu, p0[c], 2);
            p1[c] += __shfl_xor_sync(0xffffffffu, p1[c], 1);
            p1[c] += __shfl_xor_sync(0xffffffffu, p1[c], 2);
        }
        if ((l & 3) == 0) {
#pragma unroll
            for (int c = 0; c < 3; c++) {
                atomicAdd(&sacc[r0 * 3 + c], p0[c]);
                atomicAdd(&sacc[(r0 + 8) * 3 + c], p1[c]);
            }
        }
    }
    __syncthreads();

    for (int i = t; i < 384; i += 256) {
        const int row = i / 3, c = i % 3;
        atomicAdd(&g_acc[((size_t)e * Bn + m0 + row) * Cn + c], sacc[i]);
    }
}

// ---------------------------------------------------------------------
// Kernel 4: out[b,c] = sum_e gw[b,e] * (acc[e,b,c] + b2[e,c])
// ---------------------------------------------------------------------
__global__ void finalize_kernel(const float* __restrict__ ex_b2,
                                float* __restrict__ out) {
    int idx = blockIdx.x * 256 + threadIdx.x;
    if (idx >= Bn * Cn) return;
    int b = idx / Cn, c = idx % Cn;
    float s = 0.0f;
#pragma unroll
    for (int e = 0; e < En; e++) {
        float logit = g_acc[((size_t)e * Bn + b) * Cn + c] + ex_b2[e * Cn + c];
        s = fmaf(g_gw[b * En + e], logit, s);
    }
    out[idx] = s;
}

// ---------------------------------------------------------------------
extern "C" void kernel_launch(void* const* d_in, const int* in_sizes, int n_in,
                              void* d_out, int out_size) {
    const float* x         = (const float*)d_in[0];
    const float* gate_ln_g = (const float*)d_in[1];
    const float* gate_ln_b = (const float*)d_in[2];
    const float* gate_w    = (const float*)d_in[3];
    const float* gate_b    = (const float*)d_in[4];
    const float* ex_ln_g   = (const float*)d_in[5];
    const float* ex_ln_b   = (const float*)d_in[6];
    const float* ex_w1     = (const float*)d_in[7];
    const float* ex_b1     = (const float*)d_in[8];
    const float* ex_w2     = (const float*)d_in[9];
    const float* ex_b2     = (const float*)d_in[10];
    float* out = (float*)d_out;

    cudaFuncSetAttribute(moe_gemm_tc_kernel,
                         cudaFuncAttributeMaxDynamicSharedMemorySize, SMEM_TOTAL);

    init_kernel<<<(En * Bn * Cn + 255) / 256, 256>>>(ex_b1);
    prep_w1t_kernel<<<dim3(Dn / 32, Hn / 32, En), dim3(32, 8)>>>(ex_ln_g, ex_ln_b, ex_w1);
    norm_gate_kernel<<<Bn, 256>>>(x, gate_ln_g, gate_ln_b, gate_w, gate_b);
    moe_gemm_tc_kernel<<<dim3(Hn / BN, Bn / BM, En), 256, SMEM_TOTAL>>>(ex_w2);
    finalize_kernel<<<(Bn * Cn + 255) / 256, 256>>>(ex_b2, out);
}